// round 1
// baseline (speedup 1.0000x reference)
#include <cuda_runtime.h>
#include <cuda_bf16.h>

// out[row, k] = clips[row, k - idx] for k >= idx else 0, idx = int(x[row] * N).
// Rows = B*C = 1024, N = 32768. Pure bandwidth kernel: float4 stores, aligned
// float4 loads with a per-row-uniform component rotation (idx constant per
// row => no intra-block divergence on the alignment branch).

#define PLACE_NTHREADS 256

__global__ void RollScheduler_63273458204913_kernel(
    const float* __restrict__ x,
    const float* __restrict__ clips,
    float* __restrict__ out,
    int n)
{
    const int row = blockIdx.y;
    // Match jnp: (x * n).astype(int32) — f32 multiply, truncate toward zero.
    const int idx = (int)(x[row] * (float)n);

    const float* __restrict__ src = clips + (size_t)row * (size_t)n;
    float*       __restrict__ dst = out   + (size_t)row * (size_t)n;

    const int k = (blockIdx.x * PLACE_NTHREADS + threadIdx.x) * 4;
    if (k >= n) return;

    const int base = k - idx;  // source index of component 0
    float4 v;

    if (base >= 0) {
        const int r = base & 3;  // uniform across the block (idx per-row const)
        if (r == 0) {
            v = *reinterpret_cast<const float4*>(src + base);
        } else {
            const int a = base - r;  // aligned
            if (a + 7 < n) {
                const float4 lo = *reinterpret_cast<const float4*>(src + a);
                const float4 hi = *reinterpret_cast<const float4*>(src + a + 4);
                if (r == 1)      v = make_float4(lo.y, lo.z, lo.w, hi.x);
                else if (r == 2) v = make_float4(lo.z, lo.w, hi.x, hi.y);
                else             v = make_float4(lo.w, hi.x, hi.y, hi.z);
            } else {
                // Last few elements of the row: scalar tail, stay in-bounds.
                v.x = src[base];
                v.y = (base + 1 < n) ? src[base + 1] : 0.0f;
                v.z = (base + 2 < n) ? src[base + 2] : 0.0f;
                v.w = (base + 3 < n) ? src[base + 3] : 0.0f;
            }
        }
    } else if (base + 3 < 0) {
        v = make_float4(0.0f, 0.0f, 0.0f, 0.0f);
    } else {
        // Straddles the shift boundary (at most one float4 per row).
        v.x = (base     >= 0) ? src[base]     : 0.0f;
        v.y = (base + 1 >= 0) ? src[base + 1] : 0.0f;
        v.z = (base + 2 >= 0) ? src[base + 2] : 0.0f;
        v.w = (base + 3 >= 0) ? src[base + 3] : 0.0f;
    }

    *reinterpret_cast<float4*>(dst + k) = v;
}

extern "C" void kernel_launch(void* const* d_in, const int* in_sizes, int n_in,
                              void* d_out, int out_size) {
    const float* x     = (const float*)d_in[0];   // (B, C)
    const float* clips = (const float*)d_in[1];   // (B, C, N)
    // d_in[2] = actual — unused in forward.
    float* out = (float*)d_out;

    const int rows = in_sizes[0];                 // B*C
    const int n    = in_sizes[1] / in_sizes[0];   // N

    dim3 block(PLACE_NTHREADS);
    dim3 grid((n + 4 * PLACE_NTHREADS - 1) / (4 * PLACE_NTHREADS), rows);
    RollScheduler_63273458204913_kernel<<<grid, block>>>(x, clips, out, n);
}

// round 2
// speedup vs baseline: 1.0640x; 1.0640x over previous
#include <cuda_runtime.h>
#include <cuda_bf16.h>

// out[row, k] = clips[row, k - idx] for k >= idx else 0, idx = int(x[row]*N).
// rows = B*C = 1024, N = 32768, fp32. Streaming-bandwidth kernel.
//
// R2: deep per-thread unroll (8 independent float4 chunks per thread) to get
// MLP ~8 and cut the grid from 32768 blocks (~28 waves) to 4096 (~3.5 waves).
// Alignment remainder r = (-idx)&3 is per-row constant => block-uniform
// switch selects a compile-time-specialized rotation loop (no divergence).

#define BLOCK   256
#define UNROLL  8
#define SEG     (BLOCK * 4 * UNROLL)   // 8192 floats per block

__device__ __forceinline__ float4 ld128(const float* p) {
    return *reinterpret_cast<const float4*>(p);
}

__global__ void RollScheduler_63273458204913_kernel(
    const float* __restrict__ x,
    const float* __restrict__ clips,
    float* __restrict__ out,
    int n)
{
    const int row = blockIdx.y;
    // Match jnp: (x * n).astype(int32) — f32 multiply, truncate toward zero.
    const int idx = (int)(x[row] * (float)n);

    const float* __restrict__ src = clips + (size_t)row * (size_t)n;
    float*       __restrict__ dst = out   + (size_t)row * (size_t)n;

    const int k0 = blockIdx.x * SEG + threadIdx.x * 4;
    const int r  = (4 - (idx & 3)) & 3;   // = (k - idx) & 3 for any k%4==0

    // Generic guarded chunk (boundary straddle / near-end tail). All base+j
    // stay < n because k+j < n and idx >= 0; only the >=0 guard is needed.
    #define GUARDED_CHUNK(k, base, v)                                  \
        do {                                                           \
            (v).x = ((base)     >= 0) ? src[(base)]     : 0.0f;        \
            (v).y = ((base) + 1 >= 0) ? src[(base) + 1] : 0.0f;        \
            (v).z = ((base) + 2 >= 0) ? src[(base) + 2] : 0.0f;        \
            (v).w = ((base) + 3 >= 0) ? src[(base) + 3] : 0.0f;        \
        } while (0)

    #define BODY(R)                                                            \
        _Pragma("unroll")                                                      \
        for (int u = 0; u < UNROLL; u++) {                                     \
            const int k = k0 + u * (BLOCK * 4);                                \
            if (k >= n) break;                                                 \
            const int base = k - idx;                                          \
            float4 v;                                                          \
            if ((R) == 0) {                                                    \
                if (base >= 0)            v = ld128(src + base);               \
                else if (base + 3 < 0)    v = make_float4(0.f, 0.f, 0.f, 0.f); \
                else                      GUARDED_CHUNK(k, base, v);           \
            } else {                                                           \
                const int a = base - (R);                                      \
                if (a >= 0 && a + 8 <= n) {                                    \
                    const float4 lo = ld128(src + a);                          \
                    const float4 hi = ld128(src + a + 4);                      \
                    v = ((R) == 1) ? make_float4(lo.y, lo.z, lo.w, hi.x)       \
                      : ((R) == 2) ? make_float4(lo.z, lo.w, hi.x, hi.y)       \
                                   : make_float4(lo.w, hi.x, hi.y, hi.z);      \
                } else if (base + 3 < 0) {                                     \
                    v = make_float4(0.f, 0.f, 0.f, 0.f);                       \
                } else {                                                       \
                    GUARDED_CHUNK(k, base, v);                                 \
                }                                                              \
            }                                                                  \
            *reinterpret_cast<float4*>(dst + k) = v;                           \
        }

    switch (r) {            // block-uniform: idx is constant per row
        case 0: BODY(0); break;
        case 1: BODY(1); break;
        case 2: BODY(2); break;
        default: BODY(3); break;
    }

    #undef BODY
    #undef GUARDED_CHUNK
}

extern "C" void kernel_launch(void* const* d_in, const int* in_sizes, int n_in,
                              void* d_out, int out_size) {
    const float* x     = (const float*)d_in[0];   // (B, C)
    const float* clips = (const float*)d_in[1];   // (B, C, N)
    // d_in[2] = actual — unused in the forward computation.
    float* out = (float*)d_out;

    const int rows = in_sizes[0];                 // B*C = 1024
    const int n    = in_sizes[1] / in_sizes[0];   // N = 32768

    dim3 block(BLOCK);
    dim3 grid((n + SEG - 1) / SEG, rows);
    RollScheduler_63273458204913_kernel<<<grid, block>>>(x, clips, out, n);
}